// round 2
// baseline (speedup 1.0000x reference)
#include <cuda_runtime.h>
#include <math.h>

#define G 2048
#define F 128
#define IN0 144
#define TM 64
#define EPS 1e-5f

// ---------------- scratch (device globals: no allocations allowed) ----------
__device__ float d_hbuf[500000 * 128];     // relu(deepset1) output
__device__ int   d_off[G + 1];             // graph start offsets (batch is sorted)
__device__ float d_xm[G * IN0];            // segment mean of x0
__device__ float d_lam1[G * F];            // xm @ l1w^T
__device__ float d_hm[G * F];              // segment mean of h
__device__ float d_lam2[G * F];            // hm @ l2w^T
__device__ float d_S[2 * F];               // BN sum / sumsq accumulators
__device__ float d_scale[F];
__device__ float d_shift[F];

// ---------------- K0: graph offsets via binary search (batch sorted) --------
__global__ void k_off(const int* __restrict__ batch, int N) {
    int g = blockIdx.x * blockDim.x + threadIdx.x;
    if (g > G) return;
    int lo = 0, hi = N;
    while (lo < hi) { int mid = (lo + hi) >> 1; if (batch[mid] < g) lo = mid + 1; else hi = mid; }
    d_off[g] = lo;
}

// ---------------- K1: xm = segment_mean(x0) ; x0 = [x | pers gather] --------
__global__ void k_xm(const float* __restrict__ x, const float* __restrict__ pers, int N) {
    int g = blockIdx.x;
    int j = threadIdx.x;            // 160 threads, 144 active
    if (j >= IN0) return;
    int s = d_off[g], e = d_off[g + 1];
    float acc = 0.f;
    if (j < F) {
        const float* p = x + j;
        #pragma unroll 4
        for (int n = s; n < e; ++n) acc += p[(size_t)n * F];
    } else {
        int jj = j - F; int pp = jj >> 1; int c = jj & 1;
        const float* p = pers + (size_t)pp * N * 2 + c;
        #pragma unroll 4
        for (int n = s; n < e; ++n) acc += p[(size_t)n * 2];
    }
    d_xm[g * IN0 + j] = acc / fmaxf((float)(e - s), 1.f);
}

// ---------------- K2: lam1 = xm @ l1w^T  (2048 x 128, K=144) ----------------
__global__ void k_lam1(const float* __restrict__ l1w) {
    __shared__ float mr[IN0];
    int g = blockIdx.x, j = threadIdx.x;   // 128 threads
    for (int k = j; k < IN0; k += 128) mr[k] = d_xm[g * IN0 + k];
    __syncthreads();
    float acc = 0.f;
    const float* w = l1w + j * IN0;
    #pragma unroll 4
    for (int k = 0; k < IN0; ++k) acc += mr[k] * w[k];
    d_lam1[g * F + j] = acc;
}

// ---------------- K3: h = relu(x0 @ g1w^T + g1b - lam1[batch]) --------------
#define SA 148
__global__ void k_gemm1(const float* __restrict__ x, const float* __restrict__ pers,
                        const int* __restrict__ batch,
                        const float* __restrict__ g1w, const float* __restrict__ g1b,
                        int N) {
    extern __shared__ float sm[];
    float* wt = sm;                  // 144*128 : wt[k*128+j] = g1w[j*144+k]
    float* as = sm + IN0 * F;        // 64*148
    int*   bs = (int*)(as + TM * SA);
    int tid = threadIdx.x;
    int n0 = blockIdx.x * TM;

    for (int idx = tid; idx < IN0 * F; idx += 256) {
        int k = idx >> 7, j = idx & 127;
        wt[idx] = g1w[j * IN0 + k];
    }
    for (int idx = tid; idx < TM * 32; idx += 256) {
        int r = idx >> 5, c4 = idx & 31;
        int n = n0 + r;
        float4 v = (n < N) ? *(const float4*)&x[(size_t)n * F + c4 * 4]
                           : make_float4(0.f, 0.f, 0.f, 0.f);
        *(float4*)&as[r * SA + c4 * 4] = v;
    }
    for (int idx = tid; idx < TM * 16; idx += 256) {
        int r = idx >> 4, jj = idx & 15;
        int n = n0 + r;
        int pp = jj >> 1, c = jj & 1;
        as[r * SA + F + jj] = (n < N) ? pers[(size_t)pp * N * 2 + (size_t)n * 2 + c] : 0.f;
    }
    if (tid < TM) { int n = n0 + tid; bs[tid] = (n < N) ? batch[n] : 0; }
    __syncthreads();

    int tx = tid & 31, ty = tid >> 5;
    float acc[8][4];
    #pragma unroll
    for (int r = 0; r < 8; ++r)
        { acc[r][0] = 0.f; acc[r][1] = 0.f; acc[r][2] = 0.f; acc[r][3] = 0.f; }

    const float* arow = as + ty * 8 * SA;
    #pragma unroll 4
    for (int k = 0; k < IN0; ++k) {
        float4 w = *(float4*)&wt[k * F + tx * 4];
        #pragma unroll
        for (int r = 0; r < 8; ++r) {
            float a = arow[r * SA + k];
            acc[r][0] += a * w.x; acc[r][1] += a * w.y;
            acc[r][2] += a * w.z; acc[r][3] += a * w.w;
        }
    }
    float4 bias = *(const float4*)&g1b[tx * 4];
    #pragma unroll
    for (int r = 0; r < 8; ++r) {
        int row = ty * 8 + r;
        int n = n0 + row;
        if (n < N) {
            float4 l = *(const float4*)&d_lam1[bs[row] * F + tx * 4];
            float4 o;
            o.x = fmaxf(acc[r][0] + bias.x - l.x, 0.f);
            o.y = fmaxf(acc[r][1] + bias.y - l.y, 0.f);
            o.z = fmaxf(acc[r][2] + bias.z - l.z, 0.f);
            o.w = fmaxf(acc[r][3] + bias.w - l.w, 0.f);
            *(float4*)&d_hbuf[(size_t)n * F + tx * 4] = o;
        }
    }
}

// ---------------- K4: hm = segment_mean(h) ----------------------------------
__global__ void k_hm() {
    int g = blockIdx.x, j = threadIdx.x;   // 128 threads
    int s = d_off[g], e = d_off[g + 1];
    float acc = 0.f;
    const float* p = d_hbuf + j;
    #pragma unroll 4
    for (int n = s; n < e; ++n) acc += p[(size_t)n * F];
    d_hm[g * F + j] = acc / fmaxf((float)(e - s), 1.f);
}

// ---------------- K5: lam2 = hm @ l2w^T -------------------------------------
__global__ void k_lam2(const float* __restrict__ l2w) {
    __shared__ float mr[F];
    int g = blockIdx.x, j = threadIdx.x;   // 128 threads
    mr[j] = d_hm[g * F + j];
    __syncthreads();
    float acc = 0.f;
    const float* w = l2w + j * F;
    #pragma unroll 4
    for (int k = 0; k < F; ++k) acc += mr[k] * w[k];
    d_lam2[g * F + j] = acc;
}

// ---------------- Kz: zero BN accumulators ----------------------------------
__global__ void k_zero() { d_S[threadIdx.x] = 0.f; }

// ---------------- K6: y = h @ g2w^T + g2b - lam2[batch]; BN partials --------
#define SB 132
__global__ void k_gemm2(const int* __restrict__ batch,
                        const float* __restrict__ g2w, const float* __restrict__ g2b,
                        int N, float* __restrict__ y) {
    extern __shared__ float sm[];
    float* wt  = sm;                    // 128*128
    float* as  = sm + F * F;            // 64*132
    float* red1 = as + TM * SB;         // 8*128
    float* red2 = red1 + 8 * F;         // 8*128
    int*   bs  = (int*)(red2 + 8 * F);
    int tid = threadIdx.x;
    int n0 = blockIdx.x * TM;

    for (int idx = tid; idx < F * F; idx += 256) {
        int k = idx >> 7, j = idx & 127;
        wt[idx] = g2w[j * F + k];
    }
    for (int idx = tid; idx < TM * 32; idx += 256) {
        int r = idx >> 5, c4 = idx & 31;
        int n = n0 + r;
        float4 v = (n < N) ? *(const float4*)&d_hbuf[(size_t)n * F + c4 * 4]
                           : make_float4(0.f, 0.f, 0.f, 0.f);
        *(float4*)&as[r * SB + c4 * 4] = v;
    }
    if (tid < TM) { int n = n0 + tid; bs[tid] = (n < N) ? batch[n] : 0; }
    __syncthreads();

    int tx = tid & 31, ty = tid >> 5;
    float acc[8][4];
    #pragma unroll
    for (int r = 0; r < 8; ++r)
        { acc[r][0] = 0.f; acc[r][1] = 0.f; acc[r][2] = 0.f; acc[r][3] = 0.f; }

    const float* arow = as + ty * 8 * SB;
    #pragma unroll 4
    for (int k = 0; k < F; ++k) {
        float4 w = *(float4*)&wt[k * F + tx * 4];
        #pragma unroll
        for (int r = 0; r < 8; ++r) {
            float a = arow[r * SB + k];
            acc[r][0] += a * w.x; acc[r][1] += a * w.y;
            acc[r][2] += a * w.z; acc[r][3] += a * w.w;
        }
    }
    float4 bias = *(const float4*)&g2b[tx * 4];
    float s1[4] = {0.f, 0.f, 0.f, 0.f}, s2[4] = {0.f, 0.f, 0.f, 0.f};
    #pragma unroll
    for (int r = 0; r < 8; ++r) {
        int row = ty * 8 + r;
        int n = n0 + row;
        if (n < N) {
            float4 l = *(const float4*)&d_lam2[bs[row] * F + tx * 4];
            float4 o;
            o.x = acc[r][0] + bias.x - l.x;
            o.y = acc[r][1] + bias.y - l.y;
            o.z = acc[r][2] + bias.z - l.z;
            o.w = acc[r][3] + bias.w - l.w;
            *(float4*)&y[(size_t)n * F + tx * 4] = o;
            s1[0] += o.x; s1[1] += o.y; s1[2] += o.z; s1[3] += o.w;
            s2[0] += o.x * o.x; s2[1] += o.y * o.y; s2[2] += o.z * o.z; s2[3] += o.w * o.w;
        }
    }
    #pragma unroll
    for (int c = 0; c < 4; ++c) {
        red1[ty * F + tx * 4 + c] = s1[c];
        red2[ty * F + tx * 4 + c] = s2[c];
    }
    __syncthreads();
    if (tid < F) {
        float a = 0.f, b = 0.f;
        #pragma unroll
        for (int t = 0; t < 8; ++t) { a += red1[t * F + tid]; b += red2[t * F + tid]; }
        atomicAdd(&d_S[tid], a);
        atomicAdd(&d_S[F + tid], b);
    }
}

// ---------------- K7: BN finalize -------------------------------------------
__global__ void k_bnfin(const float* __restrict__ bn_g, const float* __restrict__ bn_b, int N) {
    int j = threadIdx.x;
    float invN = 1.f / (float)N;
    float mu  = d_S[j] * invN;
    float var = d_S[F + j] * invN - mu * mu;
    float sc  = bn_g[j] * rsqrtf(var + EPS);
    d_scale[j] = sc;
    d_shift[j] = bn_b[j] - mu * sc;
}

// ---------------- K8: out = x + y*scale + shift (y lives in out) ------------
__global__ void k_final(const float* __restrict__ x, float* __restrict__ out, int total4) {
    int i = blockIdx.x * blockDim.x + threadIdx.x;
    if (i >= total4) return;
    int c4 = i & 31;
    float4 y  = ((float4*)out)[i];
    float4 xv = ((const float4*)x)[i];
    float4 sc = ((const float4*)d_scale)[c4];
    float4 sh = ((const float4*)d_shift)[c4];
    y.x = xv.x + y.x * sc.x + sh.x;
    y.y = xv.y + y.y * sc.y + sh.y;
    y.z = xv.z + y.z * sc.z + sh.z;
    y.w = xv.w + y.w * sc.w + sh.w;
    ((float4*)out)[i] = y;
}

// ---------------- launch -----------------------------------------------------
extern "C" void kernel_launch(void* const* d_in, const int* in_sizes, int n_in,
                              void* d_out, int out_size) {
    const float* x    = (const float*)d_in[0];
    const int*   batch= (const int*)  d_in[1];
    const float* pers = (const float*)d_in[2];
    const float* g1w  = (const float*)d_in[3];
    const float* g1b  = (const float*)d_in[4];
    const float* l1w  = (const float*)d_in[5];
    const float* g2w  = (const float*)d_in[6];
    const float* g2b  = (const float*)d_in[7];
    const float* l2w  = (const float*)d_in[8];
    const float* bn_g = (const float*)d_in[9];
    const float* bn_b = (const float*)d_in[10];
    float* out = (float*)d_out;

    int N = in_sizes[1];                 // batch element count
    int NB = (N + TM - 1) / TM;

    const int SMEM1 = (IN0 * F + TM * SA) * 4 + TM * 4;                 // k_gemm1
    const int SMEM2 = (F * F + TM * SB + 16 * F) * 4 + TM * 4;          // k_gemm2
    cudaFuncSetAttribute(k_gemm1, cudaFuncAttributeMaxDynamicSharedMemorySize, SMEM1);
    cudaFuncSetAttribute(k_gemm2, cudaFuncAttributeMaxDynamicSharedMemorySize, SMEM2);

    k_off <<<(G + 1 + 255) / 256, 256>>>(batch, N);
    k_xm  <<<G, 160>>>(x, pers, N);
    k_lam1<<<G, 128>>>(l1w);
    k_gemm1<<<NB, 256, SMEM1>>>(x, pers, batch, g1w, g1b, N);
    k_hm  <<<G, 128>>>();
    k_lam2<<<G, 128>>>(l2w);
    k_zero<<<1, 2 * F>>>();
    k_gemm2<<<NB, 256, SMEM2>>>(batch, g2w, g2b, N, out);
    k_bnfin<<<1, F>>>(bn_g, bn_b, N);
    int total4 = N * (F / 4);
    k_final<<<(total4 + 255) / 256, 256>>>(x, out, total4);
}

// round 4
// speedup vs baseline: 1.1258x; 1.1258x over previous
#include <cuda_runtime.h>
#include <math.h>

#define G 2048
#define F 128
#define IN0 144
#define TM 64
#define EPS 1e-5f

// ---------------- scratch (device globals: no allocations allowed) ----------
__device__ __align__(16) float d_hbuf[500000 * 128];
__device__ int   d_off[G + 1];
__device__ __align__(16) float d_xm[G * IN0];
__device__ __align__(16) float d_lam1[G * F];
__device__ __align__(16) float d_hm[G * F];
__device__ __align__(16) float d_lam2[G * F];
__device__ __align__(16) float d_S[2 * F];
__device__ __align__(16) float d_scale[F];
__device__ __align__(16) float d_shift[F];

// ---------------- K0: graph offsets via binary search (batch sorted) --------
__global__ void k_off(const int* __restrict__ batch, int N) {
    int g = blockIdx.x * blockDim.x + threadIdx.x;
    if (g > G) return;
    int lo = 0, hi = N;
    while (lo < hi) { int mid = (lo + hi) >> 1; if (batch[mid] < g) lo = mid + 1; else hi = mid; }
    d_off[g] = lo;
}

// ---------------- K1: xm = segment_mean(x0) ---------------------------------
__global__ void k_xm(const float* __restrict__ x, const float* __restrict__ pers, int N) {
    int g = blockIdx.x;
    int j = threadIdx.x;            // 160 threads, 144 active
    if (j >= IN0) return;
    int s = d_off[g], e = d_off[g + 1];
    float a0 = 0.f, a1 = 0.f, a2 = 0.f, a3 = 0.f;
    if (j < F) {
        const float* p = x + j;
        int n = s;
        for (; n + 3 < e; n += 4) {
            a0 += p[(size_t)n * F];
            a1 += p[(size_t)(n + 1) * F];
            a2 += p[(size_t)(n + 2) * F];
            a3 += p[(size_t)(n + 3) * F];
        }
        for (; n < e; ++n) a0 += p[(size_t)n * F];
    } else {
        int jj = j - F; int pp = jj >> 1; int c = jj & 1;
        const float* p = pers + (size_t)pp * N * 2 + c;
        int n = s;
        for (; n + 3 < e; n += 4) {
            a0 += p[(size_t)n * 2];
            a1 += p[(size_t)(n + 1) * 2];
            a2 += p[(size_t)(n + 2) * 2];
            a3 += p[(size_t)(n + 3) * 2];
        }
        for (; n < e; ++n) a0 += p[(size_t)n * 2];
    }
    d_xm[g * IN0 + j] = (a0 + a1 + a2 + a3) / fmaxf((float)(e - s), 1.f);
}

// ---------------- K2: lam1 = xm @ l1w^T -------------------------------------
__global__ void k_lam1(const float* __restrict__ l1w) {
    __shared__ float mr[IN0];
    int g = blockIdx.x, j = threadIdx.x;
    for (int k = j; k < IN0; k += 128) mr[k] = d_xm[g * IN0 + k];
    __syncthreads();
    float acc = 0.f;
    const float* w = l1w + j * IN0;
    #pragma unroll 4
    for (int k = 0; k < IN0; ++k) acc += mr[k] * w[k];
    d_lam1[g * F + j] = acc;
}

// ---------------- K3: h = relu(x0 @ g1w^T + g1b - lam1[batch]) --------------
#define SA 148
__global__ void k_gemm1(const float* __restrict__ x, const float* __restrict__ pers,
                        const int* __restrict__ batch,
                        const float* __restrict__ g1w, const float* __restrict__ g1b,
                        int N) {
    extern __shared__ float sm[];
    float* wt = sm;                  // 144*128 : wt[k*128+j] = g1w[j*144+k]
    float* as = sm + IN0 * F;        // 64*148
    int*   bs = (int*)(as + TM * SA);
    int tid = threadIdx.x;
    int n0 = blockIdx.x * TM;

    for (int idx = tid; idx < IN0 * F; idx += 256) {
        int k = idx >> 7, j = idx & 127;
        wt[idx] = g1w[j * IN0 + k];
    }
    for (int idx = tid; idx < TM * 32; idx += 256) {
        int r = idx >> 5, c4 = idx & 31;
        int n = n0 + r;
        float4 v = (n < N) ? *(const float4*)&x[(size_t)n * F + c4 * 4]
                           : make_float4(0.f, 0.f, 0.f, 0.f);
        *(float4*)&as[r * SA + c4 * 4] = v;
    }
    for (int idx = tid; idx < TM * 16; idx += 256) {
        int r = idx >> 4, jj = idx & 15;
        int n = n0 + r;
        int pp = jj >> 1, c = jj & 1;
        as[r * SA + F + jj] = (n < N) ? pers[(size_t)pp * N * 2 + (size_t)n * 2 + c] : 0.f;
    }
    if (tid < TM) { int n = n0 + tid; bs[tid] = (n < N) ? batch[n] : 0; }
    __syncthreads();

    int tx = tid & 31, ty = tid >> 5;
    float acc[8][4];
    #pragma unroll
    for (int r = 0; r < 8; ++r)
        { acc[r][0] = 0.f; acc[r][1] = 0.f; acc[r][2] = 0.f; acc[r][3] = 0.f; }

    const float* arow = as + ty * 8 * SA;
    #pragma unroll 2
    for (int k4 = 0; k4 < IN0; k4 += 4) {
        float4 a[8];
        #pragma unroll
        for (int r = 0; r < 8; ++r) a[r] = *(const float4*)&arow[r * SA + k4];
        #pragma unroll
        for (int kk = 0; kk < 4; ++kk) {
            float4 w = *(const float4*)&wt[(k4 + kk) * F + tx * 4];
            #pragma unroll
            for (int r = 0; r < 8; ++r) {
                float av = kk == 0 ? a[r].x : kk == 1 ? a[r].y : kk == 2 ? a[r].z : a[r].w;
                acc[r][0] += av * w.x; acc[r][1] += av * w.y;
                acc[r][2] += av * w.z; acc[r][3] += av * w.w;
            }
        }
    }
    float4 bias = *(const float4*)&g1b[tx * 4];
    #pragma unroll
    for (int r = 0; r < 8; ++r) {
        int row = ty * 8 + r;
        int n = n0 + row;
        if (n < N) {
            float4 l = *(const float4*)&d_lam1[bs[row] * F + tx * 4];
            float4 o;
            o.x = fmaxf(acc[r][0] + bias.x - l.x, 0.f);
            o.y = fmaxf(acc[r][1] + bias.y - l.y, 0.f);
            o.z = fmaxf(acc[r][2] + bias.z - l.z, 0.f);
            o.w = fmaxf(acc[r][3] + bias.w - l.w, 0.f);
            *(float4*)&d_hbuf[(size_t)n * F + tx * 4] = o;
        }
    }
}

// ---------------- K4: hm = segment_mean(h) ----------------------------------
__global__ void k_hm() {
    int g = blockIdx.x, j = threadIdx.x;   // 128 threads
    int s = d_off[g], e = d_off[g + 1];
    float a0 = 0.f, a1 = 0.f, a2 = 0.f, a3 = 0.f;
    const float* p = d_hbuf + j;
    int n = s;
    for (; n + 3 < e; n += 4) {
        a0 += p[(size_t)n * F];
        a1 += p[(size_t)(n + 1) * F];
        a2 += p[(size_t)(n + 2) * F];
        a3 += p[(size_t)(n + 3) * F];
    }
    for (; n < e; ++n) a0 += p[(size_t)n * F];
    d_hm[g * F + j] = (a0 + a1 + a2 + a3) / fmaxf((float)(e - s), 1.f);
}

// ---------------- K5: lam2 = hm @ l2w^T -------------------------------------
__global__ void k_lam2(const float* __restrict__ l2w) {
    __shared__ float mr[F];
    int g = blockIdx.x, j = threadIdx.x;
    mr[j] = d_hm[g * F + j];
    __syncthreads();
    float acc = 0.f;
    const float* w = l2w + j * F;
    #pragma unroll 4
    for (int k = 0; k < F; ++k) acc += mr[k] * w[k];
    d_lam2[g * F + j] = acc;
}

// ---------------- Kz: zero BN accumulators ----------------------------------
__global__ void k_zero() { d_S[threadIdx.x] = 0.f; }

// ---------------- K6: y = h @ g2w^T + g2b - lam2[batch]; BN partials --------
#define SB 132
__global__ void k_gemm2(const int* __restrict__ batch,
                        const float* __restrict__ g2w, const float* __restrict__ g2b,
                        int N, float* __restrict__ y) {
    extern __shared__ float sm[];
    float* wt  = sm;                    // 128*128
    float* as  = sm + F * F;            // 64*132
    float* red1 = as + TM * SB;         // 8*128
    float* red2 = red1 + 8 * F;         // 8*128
    int*   bs  = (int*)(red2 + 8 * F);
    int tid = threadIdx.x;
    int n0 = blockIdx.x * TM;

    for (int idx = tid; idx < F * F; idx += 256) {
        int k = idx >> 7, j = idx & 127;
        wt[idx] = g2w[j * F + k];
    }
    for (int idx = tid; idx < TM * 32; idx += 256) {
        int r = idx >> 5, c4 = idx & 31;
        int n = n0 + r;
        float4 v = (n < N) ? *(const float4*)&d_hbuf[(size_t)n * F + c4 * 4]
                           : make_float4(0.f, 0.f, 0.f, 0.f);
        *(float4*)&as[r * SB + c4 * 4] = v;
    }
    if (tid < TM) { int n = n0 + tid; bs[tid] = (n < N) ? batch[n] : 0; }
    __syncthreads();

    int tx = tid & 31, ty = tid >> 5;
    float acc[8][4];
    #pragma unroll
    for (int r = 0; r < 8; ++r)
        { acc[r][0] = 0.f; acc[r][1] = 0.f; acc[r][2] = 0.f; acc[r][3] = 0.f; }

    const float* arow = as + ty * 8 * SB;
    #pragma unroll 2
    for (int k4 = 0; k4 < F; k4 += 4) {
        float4 a[8];
        #pragma unroll
        for (int r = 0; r < 8; ++r) a[r] = *(const float4*)&arow[r * SB + k4];
        #pragma unroll
        for (int kk = 0; kk < 4; ++kk) {
            float4 w = *(const float4*)&wt[(k4 + kk) * F + tx * 4];
            #pragma unroll
            for (int r = 0; r < 8; ++r) {
                float av = kk == 0 ? a[r].x : kk == 1 ? a[r].y : kk == 2 ? a[r].z : a[r].w;
                acc[r][0] += av * w.x; acc[r][1] += av * w.y;
                acc[r][2] += av * w.z; acc[r][3] += av * w.w;
            }
        }
    }
    float4 bias = *(const float4*)&g2b[tx * 4];
    float s1[4] = {0.f, 0.f, 0.f, 0.f}, s2[4] = {0.f, 0.f, 0.f, 0.f};
    #pragma unroll
    for (int r = 0; r < 8; ++r) {
        int row = ty * 8 + r;
        int n = n0 + row;
        if (n < N) {
            float4 l = *(const float4*)&d_lam2[bs[row] * F + tx * 4];
            float4 o;
            o.x = acc[r][0] + bias.x - l.x;
            o.y = acc[r][1] + bias.y - l.y;
            o.z = acc[r][2] + bias.z - l.z;
            o.w = acc[r][3] + bias.w - l.w;
            *(float4*)&y[(size_t)n * F + tx * 4] = o;
            s1[0] += o.x; s1[1] += o.y; s1[2] += o.z; s1[3] += o.w;
            s2[0] += o.x * o.x; s2[1] += o.y * o.y; s2[2] += o.z * o.z; s2[3] += o.w * o.w;
        }
    }
    #pragma unroll
    for (int c = 0; c < 4; ++c) {
        red1[ty * F + tx * 4 + c] = s1[c];
        red2[ty * F + tx * 4 + c] = s2[c];
    }
    __syncthreads();
    if (tid < F) {
        float a = 0.f, b = 0.f;
        #pragma unroll
        for (int t = 0; t < 8; ++t) { a += red1[t * F + tid]; b += red2[t * F + tid]; }
        atomicAdd(&d_S[tid], a);
        atomicAdd(&d_S[F + tid], b);
    }
}

// ---------------- K7: BN finalize -------------------------------------------
__global__ void k_bnfin(const float* __restrict__ bn_g, const float* __restrict__ bn_b, int N) {
    int j = threadIdx.x;
    float invN = 1.f / (float)N;
    float mu  = d_S[j] * invN;
    float var = d_S[F + j] * invN - mu * mu;
    float sc  = bn_g[j] * rsqrtf(var + EPS);
    d_scale[j] = sc;
    d_shift[j] = bn_b[j] - mu * sc;
}

// ---------------- K8: out = x + y*scale + shift (y lives in out) ------------
__global__ void k_final(const float* __restrict__ x, float* __restrict__ out, int total4) {
    int i = blockIdx.x * blockDim.x + threadIdx.x;
    if (i >= total4) return;
    int c4 = i & 31;
    float4 y  = ((float4*)out)[i];
    float4 xv = ((const float4*)x)[i];
    float4 sc = ((const float4*)d_scale)[c4];
    float4 sh = ((const float4*)d_shift)[c4];
    y.x = xv.x + y.x * sc.x + sh.x;
    y.y = xv.y + y.y * sc.y + sh.y;
    y.z = xv.z + y.z * sc.z + sh.z;
    y.w = xv.w + y.w * sc.w + sh.w;
    ((float4*)out)[i] = y;
}

// ---------------- launch -----------------------------------------------------
extern "C" void kernel_launch(void* const* d_in, const int* in_sizes, int n_in,
                              void* d_out, int out_size) {
    const float* x    = (const float*)d_in[0];
    const int*   batch= (const int*)  d_in[1];
    const float* pers = (const float*)d_in[2];
    const float* g1w  = (const float*)d_in[3];
    const float* g1b  = (const float*)d_in[4];
    const float* l1w  = (const float*)d_in[5];
    const float* g2w  = (const float*)d_in[6];
    const float* g2b  = (const float*)d_in[7];
    const float* l2w  = (const float*)d_in[8];
    const float* bn_g = (const float*)d_in[9];
    const float* bn_b = (const float*)d_in[10];
    float* out = (float*)d_out;

    int N = in_sizes[1];
    int NB = (N + TM - 1) / TM;

    const int SMEM1 = (IN0 * F + TM * SA) * 4 + TM * 4;
    const int SMEM2 = (F * F + TM * SB + 16 * F) * 4 + TM * 4;
    cudaFuncSetAttribute(k_gemm1, cudaFuncAttributeMaxDynamicSharedMemorySize, SMEM1);
    cudaFuncSetAttribute(k_gemm2, cudaFuncAttributeMaxDynamicSharedMemorySize, SMEM2);

    k_off <<<(G + 1 + 255) / 256, 256>>>(batch, N);
    k_xm  <<<G, 160>>>(x, pers, N);
    k_lam1<<<G, 128>>>(l1w);
    k_gemm1<<<NB, 256, SMEM1>>>(x, pers, batch, g1w, g1b, N);
    k_hm  <<<G, 128>>>();
    k_lam2<<<G, 128>>>(l2w);
    k_zero<<<1, 2 * F>>>();
    k_gemm2<<<NB, 256, SMEM2>>>(batch, g2w, g2b, N, out);
    k_bnfin<<<1, F>>>(bn_g, bn_b, N);
    int total4 = N * (F / 4);
    k_final<<<(total4 + 255) / 256, 256>>>(x, out, total4);
}